// round 14
// baseline (speedup 1.0000x reference)
#include <cuda_runtime.h>
#include <cuda_bf16.h>
#include <cstdint>

#define B_   16
#define C_   512
#define T_   1024
#define G_   32
#define CPG  (C_ / G_)
#define EPS  1e-5f
#define QSCALE 0.04419417382415922f   // C^-1/2
#define NGRP 4
#define BG_  (B_ / NGRP)              // 4 batches per stream group

// ---------------------------------------------------------------------------
// Scratch (static __device__ — no allocation allowed)
// ---------------------------------------------------------------------------
__device__ __nv_bfloat16 g_hb [(size_t)B_ * C_ * T_];        // GN out [B,C,T]
__device__ __nv_bfloat16 g_qkv[(size_t)B_ * T_ * 3 * C_];    // [B,T,1536]
__device__ __nv_bfloat16 g_wb [(size_t)B_ * T_ * T_];        // exp(scores) bf16
__device__ float         g_rs [(size_t)B_ * T_];             // softmax row sums
__device__ __nv_bfloat16 g_ab [(size_t)B_ * T_ * C_];        // attn out [B,T,C]
__device__ __nv_bfloat16 g_wtb[(size_t)3 * C_ * C_];         // qkv weights [3C][C]
__device__ __nv_bfloat16 g_wpb[(size_t)C_ * C_];             // proj weight [C][C]
__device__ float         g_bt [3 * C_];

__device__ __forceinline__ uint32_t pk2(float a, float b) {
    __nv_bfloat162 t = __floats2bfloat162_rn(a, b);
    return *reinterpret_cast<uint32_t*>(&t);
}

// ---------------------------------------------------------------------------
// GroupNorm (all B_ batches in one launch): fp32 in, bf16 out.
// ---------------------------------------------------------------------------
__global__ __launch_bounds__(256) void groupnorm_kernel(
    const float* __restrict__ x,
    const float* __restrict__ gamma,
    const float* __restrict__ beta,
    __nv_bfloat16* __restrict__ h)
{
    const int b = blockIdx.x >> 5;
    const int g = blockIdx.x & 31;
    const size_t base = ((size_t)b * C_ + (size_t)g * CPG) * T_;
    const float4* xp = (const float4*)(x + base);
    const int N4 = CPG * T_ / 4;
    const int tid = threadIdx.x;

    float s = 0.f, s2 = 0.f;
    for (int i = tid; i < N4; i += 256) {
        float4 v = xp[i];
        s  += v.x + v.y + v.z + v.w;
        s2 += v.x * v.x + v.y * v.y + v.z * v.z + v.w * v.w;
    }
    #pragma unroll
    for (int o = 16; o > 0; o >>= 1) {
        s  += __shfl_xor_sync(0xffffffffu, s, o);
        s2 += __shfl_xor_sync(0xffffffffu, s2, o);
    }
    __shared__ float sh1[8], sh2[8];
    const int wid = tid >> 5, lane = tid & 31;
    if (lane == 0) { sh1[wid] = s; sh2[wid] = s2; }
    __syncthreads();
    if (tid == 0) {
        float a = 0.f, bb = 0.f;
        #pragma unroll
        for (int i = 0; i < 8; i++) { a += sh1[i]; bb += sh2[i]; }
        sh1[0] = a; sh2[0] = bb;
    }
    __syncthreads();
    const float inv_n = 1.0f / (float)(CPG * T_);
    const float mean = sh1[0] * inv_n;
    const float var  = sh2[0] * inv_n - mean * mean;
    const float inv  = rsqrtf(var + EPS);

    for (int i = tid; i < N4; i += 256) {
        const int c = g * CPG + (i >> 8);
        const float ga = gamma[c] * inv;
        const float be = beta[c];
        float4 v = xp[i];
        uint2 o;
        o.x = pk2((v.x - mean) * ga + be, (v.y - mean) * ga + be);
        o.y = pk2((v.z - mean) * ga + be, (v.w - mean) * ga + be);
        *(uint2*)(h + base + (size_t)i * 4) = o;
    }
}

// ---------------------------------------------------------------------------
// Pack all weights to bf16: Wq(scaled)|Wk|Wv -> g_wtb, Wp -> g_wpb.
// ---------------------------------------------------------------------------
__global__ __launch_bounds__(256) void pack_w_kernel(
    const float* __restrict__ Wq, const float* __restrict__ bq,
    const float* __restrict__ Wk, const float* __restrict__ bk,
    const float* __restrict__ Wv, const float* __restrict__ bv,
    const float* __restrict__ Wp,
    __nv_bfloat16* __restrict__ Wt, __nv_bfloat16* __restrict__ Wpb,
    float* __restrict__ bt)
{
    const int idx = blockIdx.x * 256 + threadIdx.x;   // float4 idx, 2048*128
    const int o  = idx >> 7;
    const int c4 = idx & 127;
    const float* src; float s = 1.f; __nv_bfloat16* dst;
    if (o < C_)          { src = Wq + (size_t)o * C_; s = QSCALE; dst = Wt + (size_t)o * C_; }
    else if (o < 2 * C_) { src = Wk + (size_t)(o - C_) * C_;      dst = Wt + (size_t)o * C_; }
    else if (o < 3 * C_) { src = Wv + (size_t)(o - 2 * C_) * C_;  dst = Wt + (size_t)o * C_; }
    else                 { src = Wp + (size_t)(o - 3 * C_) * C_;  dst = Wpb + (size_t)(o - 3 * C_) * C_; }
    float4 v = *(const float4*)(src + c4 * 4);
    uint2 p; p.x = pk2(v.x * s, v.y * s); p.y = pk2(v.z * s, v.w * s);
    *(uint2*)(dst + c4 * 4) = p;
    if (idx < 3 * C_) {
        bt[idx] = (idx < C_) ? bq[idx] * QSCALE
                : (idx < 2 * C_) ? bk[idx - C_] : bv[idx - 2 * C_];
    }
}

// ---------------------------------------------------------------------------
// bf16 GEMM, cp.async 4-stage pipeline. Block tile 128x128, BK=32,
// 128 threads / 4 warps (2x2), warp tile 64x64. 2 CTAs/SM.
// AT/BT: 0 = [row][k] k-contig, 1 = [k][row] row-contig (trans ldmatrix).
// OUTBF: bf16 output.  EXPO: epilogue exp + row-sum atomics into rsum.
// NORM: epilogue multiplies by 1/rsum[row] (softmax normalization).
// ---------------------------------------------------------------------------
__device__ __forceinline__ void ldsm4(uint32_t* r, uint32_t a) {
    asm volatile("ldmatrix.sync.aligned.m8n8.x4.shared.b16 {%0,%1,%2,%3}, [%4];"
                 : "=r"(r[0]), "=r"(r[1]), "=r"(r[2]), "=r"(r[3]) : "r"(a));
}
__device__ __forceinline__ void ldsm4t(uint32_t* r, uint32_t a) {
    asm volatile("ldmatrix.sync.aligned.m8n8.x4.trans.shared.b16 {%0,%1,%2,%3}, [%4];"
                 : "=r"(r[0]), "=r"(r[1]), "=r"(r[2]), "=r"(r[3]) : "r"(a));
}
__device__ __forceinline__ void mma16(float* c, const uint32_t* a, const uint32_t* b) {
    asm volatile("mma.sync.aligned.m16n8k16.row.col.f32.bf16.bf16.f32 "
                 "{%0,%1,%2,%3},{%4,%5,%6,%7},{%8,%9},{%0,%1,%2,%3};"
                 : "+f"(c[0]), "+f"(c[1]), "+f"(c[2]), "+f"(c[3])
                 : "r"(a[0]), "r"(a[1]), "r"(a[2]), "r"(a[3]), "r"(b[0]), "r"(b[1]));
}
__device__ __forceinline__ void cpa16(uint32_t dst, const void* src) {
    asm volatile("cp.async.cg.shared.global [%0], [%1], 16;" :: "r"(dst), "l"(src));
}
#define CP_COMMIT() asm volatile("cp.async.commit_group;")
#define CP_WAIT2()  asm volatile("cp.async.wait_group 2;")

#define ABUF_OFF 0
#define BBUF_OFF 10240
#define BUFSTEP  20480
#define STAGES   4
#define SMEM_DYN (STAGES * BUFSTEP)

template<int AT, int BT, int OUTBF, int EXPO, int NORM>
__global__ __launch_bounds__(128, 2) void gemm_ca(
    int N, int K,
    const __nv_bfloat16* __restrict__ A, size_t Abs, int lda,
    const __nv_bfloat16* __restrict__ Bp, size_t Bbs, int ldb,
    void* __restrict__ Cvp, size_t Cbs,
    const float* __restrict__ bias, int bias_on_n,
    const float* __restrict__ resid, size_t Rbs,
    float* __restrict__ rsum)
{
    const int bz = blockIdx.z;
    A  += (size_t)bz * Abs;
    Bp += (size_t)bz * Bbs;
    if (resid) resid += (size_t)bz * Rbs;

    extern __shared__ __align__(16) unsigned char sm[];
    const uint32_t sb = (uint32_t)__cvta_generic_to_shared(sm);

    const int tid = threadIdx.x;
    const int m0 = blockIdx.y * 128;
    const int n0 = blockIdx.x * 128;
    const int warp = tid >> 5, lane = tid & 31;
    const int wm = warp >> 1, wn = warp & 1;     // 2x2 warp grid, 64x64 tiles
    const int gid = lane >> 2, tig = lane & 3;

    float acc[4][8][4];
    #pragma unroll
    for (int i = 0; i < 4; i++)
        #pragma unroll
        for (int j = 0; j < 8; j++)
            #pragma unroll
            for (int r = 0; r < 4; r++) acc[i][j][r] = 0.f;

    // --- cp.async: 128 threads, 4 passes each for A (8KB) and B (8KB) ---
    const __nv_bfloat16 *aS, *bS;
    uint32_t aD, bD;
    size_t aStep, bStep, aPassS, bPassS;
    uint32_t aPassD, bPassD;
    if (AT == 0) {
        aS = A + (size_t)(m0 + (tid >> 2)) * lda + (tid & 3) * 8;
        aD = ABUF_OFF + (tid >> 2) * 80 + (tid & 3) * 16;
        aPassS = (size_t)32 * lda; aPassD = 32 * 80;
        aStep = 32;
    } else {
        aS = A + (size_t)(tid >> 4) * lda + m0 + (tid & 15) * 8;
        aD = ABUF_OFF + (tid >> 4) * 272 + (tid & 15) * 16;
        aPassS = (size_t)8 * lda; aPassD = 8 * 272;
        aStep = (size_t)32 * lda;
    }
    if (BT == 0) {
        bS = Bp + (size_t)(n0 + (tid >> 2)) * ldb + (tid & 3) * 8;
        bD = BBUF_OFF + (tid >> 2) * 80 + (tid & 3) * 16;
        bPassS = (size_t)32 * ldb; bPassD = 32 * 80;
        bStep = 32;
    } else {
        bS = Bp + (size_t)(tid >> 4) * ldb + n0 + (tid & 15) * 8;
        bD = BBUF_OFF + (tid >> 4) * 272 + (tid & 15) * 16;
        bPassS = (size_t)8 * ldb; bPassD = 8 * 272;
        bStep = (size_t)32 * ldb;
    }
    auto issueBuf = [&](uint32_t bufb) {
        #pragma unroll
        for (int p = 0; p < 4; p++)
            cpa16(bufb + aD + p * aPassD, aS + p * aPassS);
        #pragma unroll
        for (int p = 0; p < 4; p++)
            cpa16(bufb + bD + p * bPassD, bS + p * bPassS);
        aS += aStep; bS += bStep;
    };

    // ldmatrix base addresses (buffer 0)
    const uint32_t aBase = (AT == 0)
        ? sb + ABUF_OFF + (uint32_t)(wm * 64 + (lane & 15)) * 80 + ((lane >> 4) & 1) * 16
        : sb + ABUF_OFF + (uint32_t)(((lane >> 4) & 1) * 8 + (lane & 7)) * 272
                        + (uint32_t)(wm * 64 + ((lane >> 3) & 1) * 8) * 2;
    const uint32_t bBase = (BT == 0)
        ? sb + BBUF_OFF + (uint32_t)(wn * 64 + ((lane >> 4) & 1) * 8 + (lane & 7)) * 80
                        + ((lane >> 3) & 1) * 16
        : sb + BBUF_OFF + (uint32_t)(((lane >> 3) & 1) * 8 + (lane & 7)) * 272
                        + (uint32_t)(wn * 64 + ((lane >> 4) & 1) * 8) * 2;

    const int nIter = K >> 5;     // multiple of 4 for all our shapes
    issueBuf(sb + 0 * BUFSTEP); CP_COMMIT();
    issueBuf(sb + 1 * BUFSTEP); CP_COMMIT();
    issueBuf(sb + 2 * BUFSTEP); CP_COMMIT();

    for (int itb = 0; itb < nIter; itb += 4) {
        #pragma unroll
        for (int u = 0; u < 4; u++) {
            const int it = itb + u;
            CP_WAIT2();
            __syncthreads();

            const uint32_t aB = aBase + u * BUFSTEP;
            const uint32_t bB = bBase + u * BUFSTEP;

            // ---- load all fragments (both kk halves) up front ----
            uint32_t af[2][4][4], bf[2][4][4];
            #pragma unroll
            for (int mi = 0; mi < 4; mi++) {
                const uint32_t ad = (AT == 0) ? aB + mi * 1280 : aB + mi * 32;
                if (AT == 0) ldsm4(af[0][mi], ad); else ldsm4t(af[0][mi], ad);
            }
            #pragma unroll
            for (int np = 0; np < 4; np++) {
                const uint32_t bd = (BT == 0) ? bB + np * 1280 : bB + np * 32;
                if (BT == 0) ldsm4(bf[0][np], bd); else ldsm4t(bf[0][np], bd);
            }
            if (it + 3 < nIter) issueBuf(sb + ((u + 3) & 3) * BUFSTEP);
            CP_COMMIT();
            #pragma unroll
            for (int mi = 0; mi < 4; mi++) {
                const uint32_t ad = (AT == 0) ? aB + mi * 1280 + 32
                                              : aB + 4352 + mi * 32;
                if (AT == 0) ldsm4(af[1][mi], ad); else ldsm4t(af[1][mi], ad);
            }
            #pragma unroll
            for (int np = 0; np < 4; np++) {
                const uint32_t bd = (BT == 0) ? bB + np * 1280 + 32
                                              : bB + 4352 + np * 32;
                if (BT == 0) ldsm4(bf[1][np], bd); else ldsm4t(bf[1][np], bd);
            }

            // ---- 128 MMAs back-to-back ----
            #pragma unroll
            for (int kk = 0; kk < 2; kk++)
                #pragma unroll
                for (int mi = 0; mi < 4; mi++)
                    #pragma unroll
                    for (int nj = 0; nj < 8; nj++)
                        mma16(acc[mi][nj], af[kk][mi], &bf[kk][nj >> 1][(nj & 1) * 2]);
        }
    }

    // ---- epilogue ----
    #pragma unroll
    for (int mi = 0; mi < 4; mi++) {
        float rs[2] = {0.f, 0.f};
        float invr[2] = {1.f, 1.f};
        if (NORM) {
            #pragma unroll
            for (int hh = 0; hh < 2; hh++) {
                const int row = m0 + wm * 64 + mi * 16 + gid + hh * 8;
                invr[hh] = 1.0f / rsum[(size_t)bz * T_ + row];
            }
        }
        #pragma unroll
        for (int nj = 0; nj < 8; nj++) {
            const int cc = n0 + wn * 64 + nj * 8 + tig * 2;
            float bn0 = 0.f, bn1 = 0.f;
            if (bias && bias_on_n) { bn0 = bias[cc]; bn1 = bias[cc + 1]; }
            #pragma unroll
            for (int hh = 0; hh < 2; hh++) {
                const int row = m0 + wm * 64 + mi * 16 + gid + hh * 8;
                float v0 = acc[mi][nj][hh * 2 + 0];
                float v1 = acc[mi][nj][hh * 2 + 1];
                if (bias) {
                    if (bias_on_n) { v0 += bn0; v1 += bn1; }
                    else { const float bm = bias[row]; v0 += bm; v1 += bm; }
                }
                if (EXPO) {
                    v0 = __expf(v0); v1 = __expf(v1);
                    rs[hh] += v0 + v1;
                }
                if (NORM) { v0 *= invr[hh]; v1 *= invr[hh]; }
                if (resid) {
                    const float2 rr = *(const float2*)&resid[(size_t)row * N + cc];
                    v0 += rr.x; v1 += rr.y;
                }
                if (OUTBF) {
                    __nv_bfloat16* Cb = (__nv_bfloat16*)Cvp + (size_t)bz * Cbs;
                    *(uint32_t*)&Cb[(size_t)row * N + cc] = pk2(v0, v1);
                } else {
                    float* Cf = (float*)Cvp + (size_t)bz * Cbs;
                    float2 o; o.x = v0; o.y = v1;
                    *(float2*)&Cf[(size_t)row * N + cc] = o;
                }
            }
        }
        if (EXPO) {
            #pragma unroll
            for (int hh = 0; hh < 2; hh++) {
                float v = rs[hh];
                v += __shfl_xor_sync(0xffffffffu, v, 1);
                v += __shfl_xor_sync(0xffffffffu, v, 2);
                if (tig == 0) {
                    const int row = m0 + wm * 64 + mi * 16 + gid + hh * 8;
                    atomicAdd(&rsum[(size_t)bz * T_ + row], v);
                }
            }
        }
    }
}

// ---------------------------------------------------------------------------
// Launch: 4 stream-groups of 4 batches (3 created streams — proven budget).
// Preamble parallelized: pack on st0, GN(all batches) on st1, memset on st2.
// ---------------------------------------------------------------------------
extern "C" void kernel_launch(void* const* d_in, const int* in_sizes, int n_in,
                              void* d_out, int out_size)
{
    const float* x     = (const float*)d_in[0];
    const float* gamma = (const float*)d_in[1];
    const float* beta  = (const float*)d_in[2];
    const float* Wq    = (const float*)d_in[3];
    const float* bq    = (const float*)d_in[4];
    const float* Wk    = (const float*)d_in[5];
    const float* bk    = (const float*)d_in[6];
    const float* Wv    = (const float*)d_in[7];
    const float* bv    = (const float*)d_in[8];
    const float* Wp    = (const float*)d_in[9];
    const float* bp    = (const float*)d_in[10];
    float* out = (float*)d_out;

    static bool inited = false;
    static __nv_bfloat16 *p_hb, *p_qkv, *p_wb, *p_ab, *p_wtb, *p_wpb;
    static float *p_rs, *p_bt;
    static cudaStream_t st[NGRP];          // st[0] = capture/default stream
    static cudaEvent_t evFork, evInit, evGN, evMs, evJoin[NGRP];
    if (!inited) {
        cudaGetSymbolAddress((void**)&p_hb,  g_hb);
        cudaGetSymbolAddress((void**)&p_qkv, g_qkv);
        cudaGetSymbolAddress((void**)&p_wb,  g_wb);
        cudaGetSymbolAddress((void**)&p_rs,  g_rs);
        cudaGetSymbolAddress((void**)&p_ab,  g_ab);
        cudaGetSymbolAddress((void**)&p_wtb, g_wtb);
        cudaGetSymbolAddress((void**)&p_wpb, g_wpb);
        cudaGetSymbolAddress((void**)&p_bt,  g_bt);
        cudaFuncSetAttribute(gemm_ca<1, 0, 1, 0, 0>, cudaFuncAttributeMaxDynamicSharedMemorySize, SMEM_DYN);
        cudaFuncSetAttribute(gemm_ca<0, 0, 1, 1, 0>, cudaFuncAttributeMaxDynamicSharedMemorySize, SMEM_DYN);
        cudaFuncSetAttribute(gemm_ca<0, 1, 1, 0, 1>, cudaFuncAttributeMaxDynamicSharedMemorySize, SMEM_DYN);
        cudaFuncSetAttribute(gemm_ca<0, 0, 0, 0, 0>, cudaFuncAttributeMaxDynamicSharedMemorySize, SMEM_DYN);
        st[0] = 0;
        for (int i = 1; i < NGRP; i++)
            cudaStreamCreateWithFlags(&st[i], cudaStreamNonBlocking);
        cudaEventCreateWithFlags(&evFork, cudaEventDisableTiming);
        cudaEventCreateWithFlags(&evInit, cudaEventDisableTiming);
        cudaEventCreateWithFlags(&evGN,   cudaEventDisableTiming);
        cudaEventCreateWithFlags(&evMs,   cudaEventDisableTiming);
        for (int i = 1; i < NGRP; i++)
            cudaEventCreateWithFlags(&evJoin[i], cudaEventDisableTiming);
        inited = true;
    }

    const size_t sBCT = (size_t)C_ * T_;
    const size_t sQKV = (size_t)T_ * 3 * C_;
    const size_t sBTT = (size_t)T_ * T_;
    const size_t sBTC = (size_t)T_ * C_;

    // ---- fork ----
    cudaEventRecord(evFork, 0);
    for (int i = 1; i < NGRP; i++) cudaStreamWaitEvent(st[i], evFork, 0);

    // ---- parallel preamble ----
    // st0: weight pack; st1: GN over all 16 batches; st2: rsum memset.
    pack_w_kernel<<<(4 * C_ * C_ / 4) / 256, 256>>>(
        Wq, bq, Wk, bk, Wv, bv, Wp, p_wtb, p_wpb, p_bt);
    cudaEventRecord(evInit, 0);

    groupnorm_kernel<<<B_ * G_, 256, 0, st[1]>>>(x, gamma, beta, p_hb);
    cudaEventRecord(evGN, st[1]);

    cudaMemsetAsync(p_rs, 0, (size_t)B_ * T_ * sizeof(float), st[2]);
    cudaEventRecord(evMs, st[2]);

    dim3 gQKV((3 * C_) / 128, T_ / 128, BG_);
    dim3 gSco(T_ / 128, T_ / 128, BG_);
    dim3 gApp(C_ / 128, T_ / 128, BG_);
    dim3 gPro(T_ / 128, C_ / 128, BG_);

    for (int g = 0; g < NGRP; g++) {
        cudaStream_t s = st[g];
        const size_t oHB  = (size_t)g * BG_ * sBCT;
        const size_t oQKV = (size_t)g * BG_ * sQKV;
        const size_t oWB  = (size_t)g * BG_ * sBTT;
        const size_t oAB  = (size_t)g * BG_ * sBTC;
        const size_t oRS  = (size_t)g * BG_ * T_;
        const size_t oX   = oHB;

        // deps: QKV needs GN + pack; Sco epilogue needs memset.
        if (g != 0) cudaStreamWaitEvent(s, evInit, 0);
        if (g != 1) cudaStreamWaitEvent(s, evGN, 0);
        if (g != 2) cudaStreamWaitEvent(s, evMs, 0);

        gemm_ca<1, 0, 1, 0, 0><<<gQKV, 128, SMEM_DYN, s>>>(3 * C_, C_,
            p_hb + oHB, sBCT, T_,  p_wtb, 0, C_,
            p_qkv + oQKV, sQKV, p_bt, 1, nullptr, 0, nullptr);
        gemm_ca<0, 0, 1, 1, 0><<<gSco, 128, SMEM_DYN, s>>>(T_, C_,
            p_qkv + oQKV, sQKV, 3 * C_,  p_qkv + oQKV + C_, sQKV, 3 * C_,
            p_wb + oWB, sBTT, nullptr, 0, nullptr, 0, p_rs + oRS);
        gemm_ca<0, 1, 1, 0, 1><<<gApp, 128, SMEM_DYN, s>>>(C_, T_,
            p_wb + oWB, sBTT, T_,  p_qkv + oQKV + 2 * C_, sQKV, 3 * C_,
            p_ab + oAB, sBTC, nullptr, 0, nullptr, 0, p_rs + oRS);
        gemm_ca<0, 0, 0, 0, 0><<<gPro, 128, SMEM_DYN, s>>>(T_, C_,
            p_wpb, 0, C_,  p_ab + oAB, sBTC, C_,
            out + oX, sBCT, bp, 0, x + oX, sBCT, nullptr);

        if (g > 0) cudaEventRecord(evJoin[g], s);
    }

    // ---- join ----
    for (int i = 1; i < NGRP; i++) cudaStreamWaitEvent(0, evJoin[i], 0);
}

// round 15
// speedup vs baseline: 1.0051x; 1.0051x over previous
#include <cuda_runtime.h>
#include <cuda_bf16.h>
#include <cstdint>

#define B_   16
#define C_   512
#define T_   1024
#define G_   32
#define CPG  (C_ / G_)
#define EPS  1e-5f
#define QSCALE 0.04419417382415922f   // C^-1/2
#define NGRP 4
#define BG_  (B_ / NGRP)              // 4 batches per stream group

// ---------------------------------------------------------------------------
// Scratch (static __device__ — no allocation allowed)
// ---------------------------------------------------------------------------
__device__ __nv_bfloat16 g_hb [(size_t)B_ * C_ * T_];        // GN out [B,C,T]
__device__ __nv_bfloat16 g_qkv[(size_t)B_ * T_ * 3 * C_];    // [B,T,1536]
__device__ __nv_bfloat16 g_wb [(size_t)B_ * T_ * T_];        // exp(scores) bf16
__device__ float         g_rs [(size_t)B_ * T_];             // softmax row sums
__device__ __nv_bfloat16 g_ab [(size_t)B_ * T_ * C_];        // attn out [B,T,C]
__device__ __nv_bfloat16 g_wtb[(size_t)3 * C_ * C_];         // qkv weights [3C][C]
__device__ __nv_bfloat16 g_wpb[(size_t)C_ * C_];             // proj weight [C][C]
__device__ float         g_bt [3 * C_];

__device__ __forceinline__ uint32_t pk2(float a, float b) {
    __nv_bfloat162 t = __floats2bfloat162_rn(a, b);
    return *reinterpret_cast<uint32_t*>(&t);
}

// ---------------------------------------------------------------------------
// GroupNorm (per batch-group): fp32 in, bf16 out. grid = BG_*G_ blocks.
// ---------------------------------------------------------------------------
__global__ __launch_bounds__(256) void groupnorm_kernel(
    const float* __restrict__ x,
    const float* __restrict__ gamma,
    const float* __restrict__ beta,
    __nv_bfloat16* __restrict__ h)
{
    const int b = blockIdx.x >> 5;
    const int g = blockIdx.x & 31;
    const size_t base = ((size_t)b * C_ + (size_t)g * CPG) * T_;
    const float4* xp = (const float4*)(x + base);
    const int N4 = CPG * T_ / 4;
    const int tid = threadIdx.x;

    float s = 0.f, s2 = 0.f;
    for (int i = tid; i < N4; i += 256) {
        float4 v = xp[i];
        s  += v.x + v.y + v.z + v.w;
        s2 += v.x * v.x + v.y * v.y + v.z * v.z + v.w * v.w;
    }
    #pragma unroll
    for (int o = 16; o > 0; o >>= 1) {
        s  += __shfl_xor_sync(0xffffffffu, s, o);
        s2 += __shfl_xor_sync(0xffffffffu, s2, o);
    }
    __shared__ float sh1[8], sh2[8];
    const int wid = tid >> 5, lane = tid & 31;
    if (lane == 0) { sh1[wid] = s; sh2[wid] = s2; }
    __syncthreads();
    if (tid == 0) {
        float a = 0.f, bb = 0.f;
        #pragma unroll
        for (int i = 0; i < 8; i++) { a += sh1[i]; bb += sh2[i]; }
        sh1[0] = a; sh2[0] = bb;
    }
    __syncthreads();
    const float inv_n = 1.0f / (float)(CPG * T_);
    const float mean = sh1[0] * inv_n;
    const float var  = sh2[0] * inv_n - mean * mean;
    const float inv  = rsqrtf(var + EPS);

    for (int i = tid; i < N4; i += 256) {
        const int c = g * CPG + (i >> 8);
        const float ga = gamma[c] * inv;
        const float be = beta[c];
        float4 v = xp[i];
        uint2 o;
        o.x = pk2((v.x - mean) * ga + be, (v.y - mean) * ga + be);
        o.y = pk2((v.z - mean) * ga + be, (v.w - mean) * ga + be);
        *(uint2*)(h + base + (size_t)i * 4) = o;
    }
}

// ---------------------------------------------------------------------------
// Pack all weights to bf16: Wq(scaled)|Wk|Wv -> g_wtb, Wp -> g_wpb.
// ---------------------------------------------------------------------------
__global__ __launch_bounds__(256) void pack_w_kernel(
    const float* __restrict__ Wq, const float* __restrict__ bq,
    const float* __restrict__ Wk, const float* __restrict__ bk,
    const float* __restrict__ Wv, const float* __restrict__ bv,
    const float* __restrict__ Wp,
    __nv_bfloat16* __restrict__ Wt, __nv_bfloat16* __restrict__ Wpb,
    float* __restrict__ bt)
{
    const int idx = blockIdx.x * 256 + threadIdx.x;   // float4 idx, 2048*128
    const int o  = idx >> 7;
    const int c4 = idx & 127;
    const float* src; float s = 1.f; __nv_bfloat16* dst;
    if (o < C_)          { src = Wq + (size_t)o * C_; s = QSCALE; dst = Wt + (size_t)o * C_; }
    else if (o < 2 * C_) { src = Wk + (size_t)(o - C_) * C_;      dst = Wt + (size_t)o * C_; }
    else if (o < 3 * C_) { src = Wv + (size_t)(o - 2 * C_) * C_;  dst = Wt + (size_t)o * C_; }
    else                 { src = Wp + (size_t)(o - 3 * C_) * C_;  dst = Wpb + (size_t)(o - 3 * C_) * C_; }
    float4 v = *(const float4*)(src + c4 * 4);
    uint2 p; p.x = pk2(v.x * s, v.y * s); p.y = pk2(v.z * s, v.w * s);
    *(uint2*)(dst + c4 * 4) = p;
    if (idx < 3 * C_) {
        bt[idx] = (idx < C_) ? bq[idx] * QSCALE
                : (idx < 2 * C_) ? bk[idx - C_] : bv[idx - 2 * C_];
    }
}

// ---------------------------------------------------------------------------
// bf16 GEMM, cp.async 4-stage pipeline. Block tile 128x128, BK=32,
// 128 threads / 4 warps (2x2), warp tile 64x64. 2 CTAs/SM.
// AT/BT: 0 = [row][k] k-contig, 1 = [k][row] row-contig (trans ldmatrix).
// OUTBF: bf16 output.  EXPO: epilogue exp + row-sum atomics into rsum.
// NORM: epilogue multiplies by 1/rsum[row] (softmax normalization).
// ---------------------------------------------------------------------------
__device__ __forceinline__ void ldsm4(uint32_t* r, uint32_t a) {
    asm volatile("ldmatrix.sync.aligned.m8n8.x4.shared.b16 {%0,%1,%2,%3}, [%4];"
                 : "=r"(r[0]), "=r"(r[1]), "=r"(r[2]), "=r"(r[3]) : "r"(a));
}
__device__ __forceinline__ void ldsm4t(uint32_t* r, uint32_t a) {
    asm volatile("ldmatrix.sync.aligned.m8n8.x4.trans.shared.b16 {%0,%1,%2,%3}, [%4];"
                 : "=r"(r[0]), "=r"(r[1]), "=r"(r[2]), "=r"(r[3]) : "r"(a));
}
__device__ __forceinline__ void mma16(float* c, const uint32_t* a, const uint32_t* b) {
    asm volatile("mma.sync.aligned.m16n8k16.row.col.f32.bf16.bf16.f32 "
                 "{%0,%1,%2,%3},{%4,%5,%6,%7},{%8,%9},{%0,%1,%2,%3};"
                 : "+f"(c[0]), "+f"(c[1]), "+f"(c[2]), "+f"(c[3])
                 : "r"(a[0]), "r"(a[1]), "r"(a[2]), "r"(a[3]), "r"(b[0]), "r"(b[1]));
}
__device__ __forceinline__ void cpa16(uint32_t dst, const void* src) {
    asm volatile("cp.async.cg.shared.global [%0], [%1], 16;" :: "r"(dst), "l"(src));
}
#define CP_COMMIT() asm volatile("cp.async.commit_group;")
#define CP_WAIT2()  asm volatile("cp.async.wait_group 2;")

#define ABUF_OFF 0
#define BBUF_OFF 10240
#define BUFSTEP  20480
#define STAGES   4
#define SMEM_DYN (STAGES * BUFSTEP)

template<int AT, int BT, int OUTBF, int EXPO, int NORM>
__global__ __launch_bounds__(128, 2) void gemm_ca(
    int N, int K,
    const __nv_bfloat16* __restrict__ A, size_t Abs, int lda,
    const __nv_bfloat16* __restrict__ Bp, size_t Bbs, int ldb,
    void* __restrict__ Cvp, size_t Cbs,
    const float* __restrict__ bias, int bias_on_n,
    const float* __restrict__ resid, size_t Rbs,
    float* __restrict__ rsum)
{
    const int bz = blockIdx.z;
    A  += (size_t)bz * Abs;
    Bp += (size_t)bz * Bbs;
    if (resid) resid += (size_t)bz * Rbs;

    extern __shared__ __align__(16) unsigned char sm[];
    const uint32_t sb = (uint32_t)__cvta_generic_to_shared(sm);

    const int tid = threadIdx.x;
    const int m0 = blockIdx.y * 128;
    const int n0 = blockIdx.x * 128;
    const int warp = tid >> 5, lane = tid & 31;
    const int wm = warp >> 1, wn = warp & 1;     // 2x2 warp grid, 64x64 tiles
    const int gid = lane >> 2, tig = lane & 3;

    float acc[4][8][4];
    #pragma unroll
    for (int i = 0; i < 4; i++)
        #pragma unroll
        for (int j = 0; j < 8; j++)
            #pragma unroll
            for (int r = 0; r < 4; r++) acc[i][j][r] = 0.f;

    // --- cp.async: 128 threads, 4 passes each for A (8KB) and B (8KB) ---
    const __nv_bfloat16 *aS, *bS;
    uint32_t aD, bD;
    size_t aStep, bStep, aPassS, bPassS;
    uint32_t aPassD, bPassD;
    if (AT == 0) {
        aS = A + (size_t)(m0 + (tid >> 2)) * lda + (tid & 3) * 8;
        aD = ABUF_OFF + (tid >> 2) * 80 + (tid & 3) * 16;
        aPassS = (size_t)32 * lda; aPassD = 32 * 80;
        aStep = 32;
    } else {
        aS = A + (size_t)(tid >> 4) * lda + m0 + (tid & 15) * 8;
        aD = ABUF_OFF + (tid >> 4) * 272 + (tid & 15) * 16;
        aPassS = (size_t)8 * lda; aPassD = 8 * 272;
        aStep = (size_t)32 * lda;
    }
    if (BT == 0) {
        bS = Bp + (size_t)(n0 + (tid >> 2)) * ldb + (tid & 3) * 8;
        bD = BBUF_OFF + (tid >> 2) * 80 + (tid & 3) * 16;
        bPassS = (size_t)32 * ldb; bPassD = 32 * 80;
        bStep = 32;
    } else {
        bS = Bp + (size_t)(tid >> 4) * ldb + n0 + (tid & 15) * 8;
        bD = BBUF_OFF + (tid >> 4) * 272 + (tid & 15) * 16;
        bPassS = (size_t)8 * ldb; bPassD = 8 * 272;
        bStep = (size_t)32 * ldb;
    }
    auto issueBuf = [&](uint32_t bufb) {
        #pragma unroll
        for (int p = 0; p < 4; p++)
            cpa16(bufb + aD + p * aPassD, aS + p * aPassS);
        #pragma unroll
        for (int p = 0; p < 4; p++)
            cpa16(bufb + bD + p * bPassD, bS + p * bPassS);
        aS += aStep; bS += bStep;
    };

    // ldmatrix base addresses (buffer 0)
    const uint32_t aBase = (AT == 0)
        ? sb + ABUF_OFF + (uint32_t)(wm * 64 + (lane & 15)) * 80 + ((lane >> 4) & 1) * 16
        : sb + ABUF_OFF + (uint32_t)(((lane >> 4) & 1) * 8 + (lane & 7)) * 272
                        + (uint32_t)(wm * 64 + ((lane >> 3) & 1) * 8) * 2;
    const uint32_t bBase = (BT == 0)
        ? sb + BBUF_OFF + (uint32_t)(wn * 64 + ((lane >> 4) & 1) * 8 + (lane & 7)) * 80
                        + ((lane >> 3) & 1) * 16
        : sb + BBUF_OFF + (uint32_t)(((lane >> 3) & 1) * 8 + (lane & 7)) * 272
                        + (uint32_t)(wn * 64 + ((lane >> 4) & 1) * 8) * 2;

    const int nIter = K >> 5;     // multiple of 4 for all our shapes
    issueBuf(sb + 0 * BUFSTEP); CP_COMMIT();
    issueBuf(sb + 1 * BUFSTEP); CP_COMMIT();
    issueBuf(sb + 2 * BUFSTEP); CP_COMMIT();

    for (int itb = 0; itb < nIter; itb += 4) {
        #pragma unroll
        for (int u = 0; u < 4; u++) {
            const int it = itb + u;
            CP_WAIT2();
            __syncthreads();

            const uint32_t aB = aBase + u * BUFSTEP;
            const uint32_t bB = bBase + u * BUFSTEP;

            // ---- load all fragments (both kk halves) up front ----
            uint32_t af[2][4][4], bf[2][4][4];
            #pragma unroll
            for (int mi = 0; mi < 4; mi++) {
                const uint32_t ad = (AT == 0) ? aB + mi * 1280 : aB + mi * 32;
                if (AT == 0) ldsm4(af[0][mi], ad); else ldsm4t(af[0][mi], ad);
            }
            #pragma unroll
            for (int np = 0; np < 4; np++) {
                const uint32_t bd = (BT == 0) ? bB + np * 1280 : bB + np * 32;
                if (BT == 0) ldsm4(bf[0][np], bd); else ldsm4t(bf[0][np], bd);
            }
            if (it + 3 < nIter) issueBuf(sb + ((u + 3) & 3) * BUFSTEP);
            CP_COMMIT();
            #pragma unroll
            for (int mi = 0; mi < 4; mi++) {
                const uint32_t ad = (AT == 0) ? aB + mi * 1280 + 32
                                              : aB + 4352 + mi * 32;
                if (AT == 0) ldsm4(af[1][mi], ad); else ldsm4t(af[1][mi], ad);
            }
            #pragma unroll
            for (int np = 0; np < 4; np++) {
                const uint32_t bd = (BT == 0) ? bB + np * 1280 + 32
                                              : bB + 4352 + np * 32;
                if (BT == 0) ldsm4(bf[1][np], bd); else ldsm4t(bf[1][np], bd);
            }

            // ---- 128 MMAs back-to-back ----
            #pragma unroll
            for (int kk = 0; kk < 2; kk++)
                #pragma unroll
                for (int mi = 0; mi < 4; mi++)
                    #pragma unroll
                    for (int nj = 0; nj < 8; nj++)
                        mma16(acc[mi][nj], af[kk][mi], &bf[kk][nj >> 1][(nj & 1) * 2]);
        }
    }

    // ---- epilogue ----
    #pragma unroll
    for (int mi = 0; mi < 4; mi++) {
        float rs[2] = {0.f, 0.f};
        float invr[2] = {1.f, 1.f};
        if (NORM) {
            #pragma unroll
            for (int hh = 0; hh < 2; hh++) {
                const int row = m0 + wm * 64 + mi * 16 + gid + hh * 8;
                invr[hh] = 1.0f / rsum[(size_t)bz * T_ + row];
            }
        }
        #pragma unroll
        for (int nj = 0; nj < 8; nj++) {
            const int cc = n0 + wn * 64 + nj * 8 + tig * 2;
            float bn0 = 0.f, bn1 = 0.f;
            if (bias && bias_on_n) { bn0 = bias[cc]; bn1 = bias[cc + 1]; }
            #pragma unroll
            for (int hh = 0; hh < 2; hh++) {
                const int row = m0 + wm * 64 + mi * 16 + gid + hh * 8;
                float v0 = acc[mi][nj][hh * 2 + 0];
                float v1 = acc[mi][nj][hh * 2 + 1];
                if (bias) {
                    if (bias_on_n) { v0 += bn0; v1 += bn1; }
                    else { const float bm = bias[row]; v0 += bm; v1 += bm; }
                }
                if (EXPO) {
                    v0 = __expf(v0); v1 = __expf(v1);
                    rs[hh] += v0 + v1;
                }
                if (NORM) { v0 *= invr[hh]; v1 *= invr[hh]; }
                if (resid) {
                    const float2 rr = *(const float2*)&resid[(size_t)row * N + cc];
                    v0 += rr.x; v1 += rr.y;
                }
                if (OUTBF) {
                    __nv_bfloat16* Cb = (__nv_bfloat16*)Cvp + (size_t)bz * Cbs;
                    *(uint32_t*)&Cb[(size_t)row * N + cc] = pk2(v0, v1);
                } else {
                    float* Cf = (float*)Cvp + (size_t)bz * Cbs;
                    float2 o; o.x = v0; o.y = v1;
                    *(float2*)&Cf[(size_t)row * N + cc] = o;
                }
            }
        }
        if (EXPO) {
            #pragma unroll
            for (int hh = 0; hh < 2; hh++) {
                float v = rs[hh];
                v += __shfl_xor_sync(0xffffffffu, v, 1);
                v += __shfl_xor_sync(0xffffffffu, v, 2);
                if (tig == 0) {
                    const int row = m0 + wm * 64 + mi * 16 + gid + hh * 8;
                    atomicAdd(&rsum[(size_t)bz * T_ + row], v);
                }
            }
        }
    }
}

// ---------------------------------------------------------------------------
// Launch: 4 stream-groups of 4 batches, per-group GN inside the chain.
// (Measured optimum across rounds 10-14; 3 created streams = proven budget.)
// ---------------------------------------------------------------------------
extern "C" void kernel_launch(void* const* d_in, const int* in_sizes, int n_in,
                              void* d_out, int out_size)
{
    const float* x     = (const float*)d_in[0];
    const float* gamma = (const float*)d_in[1];
    const float* beta  = (const float*)d_in[2];
    const float* Wq    = (const float*)d_in[3];
    const float* bq    = (const float*)d_in[4];
    const float* Wk    = (const float*)d_in[5];
    const float* bk    = (const float*)d_in[6];
    const float* Wv    = (const float*)d_in[7];
    const float* bv    = (const float*)d_in[8];
    const float* Wp    = (const float*)d_in[9];
    const float* bp    = (const float*)d_in[10];
    float* out = (float*)d_out;

    static bool inited = false;
    static __nv_bfloat16 *p_hb, *p_qkv, *p_wb, *p_ab, *p_wtb, *p_wpb;
    static float *p_rs, *p_bt;
    static cudaStream_t st[NGRP];          // st[0] = capture/default stream
    static cudaEvent_t evFork, evInit, evJoin[NGRP];
    if (!inited) {
        cudaGetSymbolAddress((void**)&p_hb,  g_hb);
        cudaGetSymbolAddress((void**)&p_qkv, g_qkv);
        cudaGetSymbolAddress((void**)&p_wb,  g_wb);
        cudaGetSymbolAddress((void**)&p_rs,  g_rs);
        cudaGetSymbolAddress((void**)&p_ab,  g_ab);
        cudaGetSymbolAddress((void**)&p_wtb, g_wtb);
        cudaGetSymbolAddress((void**)&p_wpb, g_wpb);
        cudaGetSymbolAddress((void**)&p_bt,  g_bt);
        cudaFuncSetAttribute(gemm_ca<1, 0, 1, 0, 0>, cudaFuncAttributeMaxDynamicSharedMemorySize, SMEM_DYN);
        cudaFuncSetAttribute(gemm_ca<0, 0, 1, 1, 0>, cudaFuncAttributeMaxDynamicSharedMemorySize, SMEM_DYN);
        cudaFuncSetAttribute(gemm_ca<0, 1, 1, 0, 1>, cudaFuncAttributeMaxDynamicSharedMemorySize, SMEM_DYN);
        cudaFuncSetAttribute(gemm_ca<0, 0, 0, 0, 0>, cudaFuncAttributeMaxDynamicSharedMemorySize, SMEM_DYN);
        st[0] = 0;
        for (int i = 1; i < NGRP; i++)
            cudaStreamCreateWithFlags(&st[i], cudaStreamNonBlocking);
        cudaEventCreateWithFlags(&evFork, cudaEventDisableTiming);
        cudaEventCreateWithFlags(&evInit, cudaEventDisableTiming);
        for (int i = 1; i < NGRP; i++)
            cudaEventCreateWithFlags(&evJoin[i], cudaEventDisableTiming);
        inited = true;
    }

    const size_t sBCT = (size_t)C_ * T_;
    const size_t sQKV = (size_t)T_ * 3 * C_;
    const size_t sBTT = (size_t)T_ * T_;
    const size_t sBTC = (size_t)T_ * C_;

    // ---- fork ----
    cudaEventRecord(evFork, 0);
    for (int i = 1; i < NGRP; i++) cudaStreamWaitEvent(st[i], evFork, 0);

    // init on stream 0: rsum memset + weight pack
    cudaMemsetAsync(p_rs, 0, (size_t)B_ * T_ * sizeof(float), 0);
    pack_w_kernel<<<(4 * C_ * C_ / 4) / 256, 256>>>(
        Wq, bq, Wk, bk, Wv, bv, Wp, p_wtb, p_wpb, p_bt);
    cudaEventRecord(evInit, 0);

    dim3 gQKV((3 * C_) / 128, T_ / 128, BG_);
    dim3 gSco(T_ / 128, T_ / 128, BG_);
    dim3 gApp(C_ / 128, T_ / 128, BG_);
    dim3 gPro(T_ / 128, C_ / 128, BG_);

    for (int g = 0; g < NGRP; g++) {
        cudaStream_t s = st[g];
        const size_t oHB  = (size_t)g * BG_ * sBCT;
        const size_t oQKV = (size_t)g * BG_ * sQKV;
        const size_t oWB  = (size_t)g * BG_ * sBTT;
        const size_t oAB  = (size_t)g * BG_ * sBTC;
        const size_t oRS  = (size_t)g * BG_ * T_;
        const size_t oX   = oHB;

        // GN for this group's 4 batches (no init dependency)
        groupnorm_kernel<<<BG_ * G_, 256, 0, s>>>(x + oX, gamma, beta, p_hb + oHB);
        // QKV and onward need pack/memset
        if (g > 0) cudaStreamWaitEvent(s, evInit, 0);

        gemm_ca<1, 0, 1, 0, 0><<<gQKV, 128, SMEM_DYN, s>>>(3 * C_, C_,
            p_hb + oHB, sBCT, T_,  p_wtb, 0, C_,
            p_qkv + oQKV, sQKV, p_bt, 1, nullptr, 0, nullptr);
        gemm_ca<0, 0, 1, 1, 0><<<gSco, 128, SMEM_DYN, s>>>(T_, C_,
            p_qkv + oQKV, sQKV, 3 * C_,  p_qkv + oQKV + C_, sQKV, 3 * C_,
            p_wb + oWB, sBTT, nullptr, 0, nullptr, 0, p_rs + oRS);
        gemm_ca<0, 1, 1, 0, 1><<<gApp, 128, SMEM_DYN, s>>>(C_, T_,
            p_wb + oWB, sBTT, T_,  p_qkv + oQKV + 2 * C_, sQKV, 3 * C_,
            p_ab + oAB, sBTC, nullptr, 0, nullptr, 0, p_rs + oRS);
        gemm_ca<0, 0, 0, 0, 0><<<gPro, 128, SMEM_DYN, s>>>(T_, C_,
            p_wpb, 0, C_,  p_ab + oAB, sBTC, C_,
            out + oX, sBCT, bp, 0, x + oX, sBCT, nullptr);

        if (g > 0) cudaEventRecord(evJoin[g], s);
    }

    // ---- join ----
    for (int i = 1; i < NGRP; i++) cudaStreamWaitEvent(0, evJoin[i], 0);
}